// round 8
// baseline (speedup 1.0000x reference)
#include <cuda_runtime.h>
#include <cuda_bf16.h>
#include <math.h>

#define NN 50000
#define NE 800000
#define D  64
#define NG 128
#define DH 32
#define NC 6

// ---------------- scratch (device globals; no allocation allowed) ----------
__device__ float g_h[NN * D];         // hidden state after layer 0
__device__ float g_agg0[NN * D];      // neighbor-sum of h, layer 0
__device__ float g_agg1[NN * D];      // neighbor-sum of h, layer 1
__device__ float g_pooled[NG * D];    // graph pooling sums
__device__ int   g_cnt[NG];           // nodes per graph
__device__ float g_Wc[2 * 192 * 64];  // Wc[l][r][k] = sum_j W[l][k][j]*w_ih[r][j]

__device__ __forceinline__ float sigf(float x) {
    return __fdividef(1.f, 1.f + __expf(-x));
}
__device__ __forceinline__ float tanhfast(float x) {
    return __fdividef(2.f, 1.f + __expf(-2.f * x)) - 1.f;
}

// bf16 split helpers: v = hi + lo with |residual| ~ 2^-16 |v|
__device__ __forceinline__ void split1(float v, __nv_bfloat16& h, __nv_bfloat16& l) {
    h = __float2bfloat16(v);
    l = __float2bfloat16(v - __bfloat162float(h));
}
__device__ __forceinline__ void split_pair(float v0, float v1, unsigned& hi, unsigned& lo) {
    __nv_bfloat16 h0, l0, h1, l1;
    split1(v0, h0, l0);
    split1(v1, h1, l1);
    hi = (unsigned)__bfloat16_as_ushort(h0) | ((unsigned)__bfloat16_as_ushort(h1) << 16);
    lo = (unsigned)__bfloat16_as_ushort(l0) | ((unsigned)__bfloat16_as_ushort(l1) << 16);
}

// mma.sync m16n8k16 bf16 -> f32 accumulate
__device__ __forceinline__ void mma16816(float* c, const unsigned* a, const unsigned* b) {
    asm volatile(
        "mma.sync.aligned.m16n8k16.row.col.f32.bf16.bf16.f32 "
        "{%0,%1,%2,%3}, {%4,%5,%6,%7}, {%8,%9}, {%0,%1,%2,%3};"
        : "+f"(c[0]), "+f"(c[1]), "+f"(c[2]), "+f"(c[3])
        : "r"(a[0]), "r"(a[1]), "r"(a[2]), "r"(a[3]), "r"(b[0]), "r"(b[1]));
}

// ---------------- zero both agg buffers + pooled + counts -------------------
__global__ void k_zero() {
    int i = blockIdx.x * 256 + threadIdx.x;
    if (i < NN * D / 4) {
        ((float4*)g_agg0)[i] = make_float4(0.f, 0.f, 0.f, 0.f);
        ((float4*)g_agg1)[i] = make_float4(0.f, 0.f, 0.f, 0.f);
    }
    if (i < NG * D) g_pooled[i] = 0.f;
    if (i < NG) g_cnt[i] = 0;
}

// ---------------- per-graph node counts -------------------------------------
__global__ void k_count(const int* __restrict__ batch) {
    int n = blockIdx.x * 256 + threadIdx.x;
    if (n < NN) atomicAdd(&g_cnt[batch[n]], 1);
}

// ---------------- Wc[l] = W[l] @ w_ih^T  (stored in w_ih row layout) ---------
__global__ void k_prep(const float* __restrict__ W, const float* __restrict__ w_ih) {
    int l = blockIdx.x;
    const float* Wl = W + l * 64 * 64;
    for (int idx = threadIdx.x; idx < 192 * 64; idx += 256) {
        int r = idx >> 6, k = idx & 63;
        float s = 0.f;
#pragma unroll 16
        for (int j = 0; j < 64; j++) s += Wl[k * 64 + j] * w_ih[r * 64 + j];
        g_Wc[l * 192 * 64 + r * 64 + k] = s;
    }
}

// ---------------- edge scatter: agg[dst] += h[src] --------------------------
// One thread per (edge, 16B quad): float4 gather from L2-resident h,
// 128-bit vector atomic into agg (sm_90+ atomicAdd(float4*)).
__global__ void k_scatter(const int* __restrict__ ei, const float* __restrict__ hin,
                          float* __restrict__ agg) {
    int t = blockIdx.x * 256 + threadIdx.x;
    if (t >= NE * 16) return;
    int e = t >> 4;
    int q = t & 15;
    int src = ei[e];
    int dst = ei[NE + e];
    float4 v = *reinterpret_cast<const float4*>(&hin[src * 64 + q * 4]);
    atomicAdd(reinterpret_cast<float4*>(&agg[dst * 64 + q * 4]), v);
}

// ---------------- fused GRU gates via bf16x3 tensor cores -------------------
// gi uses agg (raw neighbor sum) with combined weight wih = Wc[l] (passed as a
// kernel PARAMETER so B-fragments stay register-resident), gh uses h with
// w_hh. Warp w owns d-slice [8w, 8w+8) of ALL six gate blocks -> full GRU
// elementwise epilogue stays in C-fragment registers.
__global__ __launch_bounds__(256, 1)
void k_gates(const float* __restrict__ hin, const float* __restrict__ agg,
             const float* __restrict__ w_ih, const float* __restrict__ w_hh,
             const float* __restrict__ b_ih, const float* __restrict__ b_hh,
             const int* __restrict__ batch, int layer) {
    __shared__ __align__(16) __nv_bfloat16 s_ahi[16 * 72];
    __shared__ __align__(16) __nv_bfloat16 s_alo[16 * 72];
    __shared__ __align__(16) __nv_bfloat16 s_hhi[16 * 72];
    __shared__ __align__(16) __nv_bfloat16 s_hlo[16 * 72];
    __shared__ __align__(16) float s_hf[16 * 66];

    int tid = threadIdx.x;
    int wid = tid >> 5, lane = tid & 31;
    int tg = lane & 3, gid = lane >> 2;
    int dbase = wid * 8;
    int d0 = dbase + tg * 2;

    // B fragments: gates 0..2 = w_ih(=Wc) rows, 3..5 = w_hh rows.
    unsigned Bhi[6][4][2], Blo[6][4][2];
#pragma unroll
    for (int g = 0; g < 6; g++) {
        const float* wm = (g < 3) ? w_ih : w_hh;
        const float* wr = wm + ((g % 3) * 64 + dbase + gid) * 64;
#pragma unroll
        for (int kt = 0; kt < 4; kt++) {
            int k0 = kt * 16 + tg * 2;
            split_pair(wr[k0],     wr[k0 + 1], Bhi[g][kt][0], Blo[g][kt][0]);
            split_pair(wr[k0 + 8], wr[k0 + 9], Bhi[g][kt][1], Blo[g][kt][1]);
        }
    }
    float bi0[2], bi1[2], bi2[2], bh0[2], bh1[2], bh2[2];
#pragma unroll
    for (int j = 0; j < 2; j++) {
        bi0[j] = b_ih[d0 + j];       bh0[j] = b_hh[d0 + j];
        bi1[j] = b_ih[64 + d0 + j];  bh1[j] = b_hh[64 + d0 + j];
        bi2[j] = b_ih[128 + d0 + j]; bh2[j] = b_hh[128 + d0 + j];
    }

    for (int chunk = blockIdx.x * 16; chunk < NN; chunk += gridDim.x * 16) {
        __syncthreads();
#pragma unroll
        for (int i = 0; i < 4; i++) {
            int idx = tid + i * 256;
            int row = idx >> 6, col = idx & 63;
            float a = agg[chunk * 64 + idx];
            float h = hin[chunk * 64 + idx];
            __nv_bfloat16 hh, ll;
            split1(a, hh, ll);
            s_ahi[row * 72 + col] = hh;
            s_alo[row * 72 + col] = ll;
            split1(h, hh, ll);
            s_hhi[row * 72 + col] = hh;
            s_hlo[row * 72 + col] = ll;
            s_hf[row * 66 + col] = h;
        }
        __syncthreads();

        float C[6][4];
#pragma unroll
        for (int g = 0; g < 6; g++)
#pragma unroll
            for (int q = 0; q < 4; q++) C[g][q] = 0.f;

#pragma unroll
        for (int kt = 0; kt < 4; kt++) {
            int k0 = kt * 16 + tg * 2;
            unsigned ahi[4], alo[4];
            // agg tile -> gates 0..2 (combined-weight i_r, i_z, i_n)
            ahi[0] = *(const unsigned*)&s_ahi[(gid)     * 72 + k0];
            ahi[1] = *(const unsigned*)&s_ahi[(gid + 8) * 72 + k0];
            ahi[2] = *(const unsigned*)&s_ahi[(gid)     * 72 + k0 + 8];
            ahi[3] = *(const unsigned*)&s_ahi[(gid + 8) * 72 + k0 + 8];
            alo[0] = *(const unsigned*)&s_alo[(gid)     * 72 + k0];
            alo[1] = *(const unsigned*)&s_alo[(gid + 8) * 72 + k0];
            alo[2] = *(const unsigned*)&s_alo[(gid)     * 72 + k0 + 8];
            alo[3] = *(const unsigned*)&s_alo[(gid + 8) * 72 + k0 + 8];
#pragma unroll
            for (int g = 0; g < 3; g++) {
                mma16816(C[g], ahi, Bhi[g][kt]);
                mma16816(C[g], ahi, Blo[g][kt]);
                mma16816(C[g], alo, Bhi[g][kt]);
            }
            // h tile -> gates 3..5 (h_r, h_z, h_n)
            ahi[0] = *(const unsigned*)&s_hhi[(gid)     * 72 + k0];
            ahi[1] = *(const unsigned*)&s_hhi[(gid + 8) * 72 + k0];
            ahi[2] = *(const unsigned*)&s_hhi[(gid)     * 72 + k0 + 8];
            ahi[3] = *(const unsigned*)&s_hhi[(gid + 8) * 72 + k0 + 8];
            alo[0] = *(const unsigned*)&s_hlo[(gid)     * 72 + k0];
            alo[1] = *(const unsigned*)&s_hlo[(gid + 8) * 72 + k0];
            alo[2] = *(const unsigned*)&s_hlo[(gid)     * 72 + k0 + 8];
            alo[3] = *(const unsigned*)&s_hlo[(gid + 8) * 72 + k0 + 8];
#pragma unroll
            for (int g = 3; g < 6; g++) {
                mma16816(C[g], ahi, Bhi[g][kt]);
                mma16816(C[g], ahi, Blo[g][kt]);
                mma16816(C[g], alo, Bhi[g][kt]);
            }
        }

        // GRU elementwise epilogue (per-thread: 2 rows x 2 dims)
#pragma unroll
        for (int p = 0; p < 2; p++) {
            int row = gid + p * 8;
            int node = chunk + row;
            float hv[2];
#pragma unroll
            for (int j = 0; j < 2; j++) {
                int q = p * 2 + j;
                float r  = sigf(C[0][q] + bi0[j] + C[3][q] + bh0[j]);
                float z  = sigf(C[1][q] + bi1[j] + C[4][q] + bh1[j]);
                float nn = tanhfast(C[2][q] + bi2[j] + r * (C[5][q] + bh2[j]));
                float ho = s_hf[row * 66 + d0 + j];
                hv[j] = (1.f - z) * nn + z * ho;
            }
            if (layer == 0) {
                *(float2*)&g_h[node * 64 + d0] = make_float2(hv[0], hv[1]);
            } else {
                float2 rv = make_float2(fmaxf(hv[0], 0.f), fmaxf(hv[1], 0.f));
                atomicAdd((float2*)&g_pooled[batch[node] * 64 + d0], rv);
            }
        }
    }
}

// ---------------- mean pool + fc1(relu) + fc2 + log_softmax -----------------
__global__ void k_poolfc(const float* __restrict__ fc1w, const float* __restrict__ fc1b,
                         const float* __restrict__ fc2w, const float* __restrict__ fc2b,
                         float* __restrict__ out) {
    int g = threadIdx.x;
    if (g >= NG) return;
    float inv = 1.f / fmaxf((float)g_cnt[g], 1.f);
    float p[D];
#pragma unroll
    for (int k = 0; k < D; k++) p[k] = g_pooled[g * D + k] * inv;

    float y[DH];
#pragma unroll
    for (int j = 0; j < DH; j++) {
        float s = fc1b[j];
#pragma unroll
        for (int k = 0; k < D; k++) s += p[k] * fc1w[j * D + k];
        y[j] = fmaxf(s, 0.f);
    }

    float z[NC];
    float mx = -1e30f;
#pragma unroll
    for (int c = 0; c < NC; c++) {
        float s = fc2b[c];
#pragma unroll
        for (int j = 0; j < DH; j++) s += y[j] * fc2w[c * DH + j];
        z[c] = s;
        mx = fmaxf(mx, s);
    }
    float lse = 0.f;
#pragma unroll
    for (int c = 0; c < NC; c++) lse += expf(z[c] - mx);
    lse = logf(lse) + mx;
#pragma unroll
    for (int c = 0; c < NC; c++) out[g * NC + c] = z[c] - lse;
}

// ---------------- launch -----------------------------------------------------
extern "C" void kernel_launch(void* const* d_in, const int* in_sizes, int n_in,
                              void* d_out, int out_size) {
    const float* x     = (const float*)d_in[0];
    const int*   ei    = (const int*)d_in[1];
    const int*   batch = (const int*)d_in[2];
    const float* W     = (const float*)d_in[3];
    const float* w_ih  = (const float*)d_in[4];
    const float* w_hh  = (const float*)d_in[5];
    const float* b_ih  = (const float*)d_in[6];
    const float* b_hh  = (const float*)d_in[7];
    const float* fc1w  = (const float*)d_in[8];
    const float* fc1b  = (const float*)d_in[9];
    const float* fc2w  = (const float*)d_in[10];
    const float* fc2b  = (const float*)d_in[11];
    float* out = (float*)d_out;

    // Resolve device-global addresses host-side so hot kernels receive plain
    // __restrict__ parameters (keeps B-fragments register-resident).
    float *p_Wc = nullptr, *p_h = nullptr, *p_agg0 = nullptr, *p_agg1 = nullptr;
    cudaGetSymbolAddress((void**)&p_Wc,   g_Wc);
    cudaGetSymbolAddress((void**)&p_h,    g_h);
    cudaGetSymbolAddress((void**)&p_agg0, g_agg0);
    cudaGetSymbolAddress((void**)&p_agg1, g_agg1);

    k_zero<<<(NN * D / 4 + 255) / 256, 256>>>();
    k_count<<<(NN + 255) / 256, 256>>>(batch);
    k_prep<<<2, 256>>>(W, w_ih);

    for (int l = 0; l < 2; l++) {
        const float* hin = l ? p_h : x;
        float* agg = l ? p_agg1 : p_agg0;
        k_scatter<<<(NE * 16) / 256, 256>>>(ei, hin, agg);
        k_gates<<<296, 256>>>(hin, agg, p_Wc + l * 192 * 64, w_hh,
                              b_ih, b_hh, batch, l);
    }
    k_poolfc<<<1, 128>>>(fc1w, fc1b, fc2w, fc2b, out);
}

// round 9
// speedup vs baseline: 2.3936x; 2.3936x over previous
#include <cuda_runtime.h>
#include <cuda_bf16.h>
#include <math.h>

#define NN 50000
#define NE 800000
#define D  64
#define NG 128
#define DH 32
#define NC 6

// ---------------- scratch (device globals; no allocation allowed) ----------
__device__ float g_h[NN * D];       // hidden state
__device__ float g_m[NN * D];       // per-node messages m = h @ W[l]
__device__ float g_agg[NN * D];     // scatter-add destination
__device__ float g_pooled[NG * D];  // graph pooling sums

__device__ __forceinline__ float sigf(float x) {
    return __fdividef(1.f, 1.f + __expf(-x));
}
__device__ __forceinline__ float tanhfast(float x) {
    return __fdividef(2.f, 1.f + __expf(-2.f * x)) - 1.f;
}

// bf16 split helpers: v = hi + lo with |residual| ~ 2^-16 |v|
__device__ __forceinline__ void split1(float v, __nv_bfloat16& h, __nv_bfloat16& l) {
    h = __float2bfloat16(v);
    l = __float2bfloat16(v - __bfloat162float(h));
}
__device__ __forceinline__ void split_pair(float v0, float v1, unsigned& hi, unsigned& lo) {
    __nv_bfloat16 h0, l0, h1, l1;
    split1(v0, h0, l0);
    split1(v1, h1, l1);
    hi = (unsigned)__bfloat16_as_ushort(h0) | ((unsigned)__bfloat16_as_ushort(h1) << 16);
    lo = (unsigned)__bfloat16_as_ushort(l0) | ((unsigned)__bfloat16_as_ushort(l1) << 16);
}
// vector split: float2 -> (bf16x2 hi word, bf16x2 lo word)
__device__ __forceinline__ void split2v(float2 v, unsigned& hi, unsigned& lo) {
    __nv_bfloat162 h = __float22bfloat162_rn(v);
    float2 r = __bfloat1622float2(h);
    __nv_bfloat162 l = __float22bfloat162_rn(make_float2(v.x - r.x, v.y - r.y));
    hi = *(unsigned*)&h;
    lo = *(unsigned*)&l;
}

// mma.sync m16n8k16 bf16 -> f32 accumulate
__device__ __forceinline__ void mma16816(float* c, const unsigned* a, const unsigned* b) {
    asm volatile(
        "mma.sync.aligned.m16n8k16.row.col.f32.bf16.bf16.f32 "
        "{%0,%1,%2,%3}, {%4,%5,%6,%7}, {%8,%9}, {%0,%1,%2,%3};"
        : "+f"(c[0]), "+f"(c[1]), "+f"(c[2]), "+f"(c[3])
        : "r"(a[0]), "r"(a[1]), "r"(a[2]), "r"(a[3]), "r"(b[0]), "r"(b[1]));
}

// ---------------- init: zero pooled sums ------------------------------------
__global__ void k_init() {
    int i = blockIdx.x * 256 + threadIdx.x;
    if (i < NG * D) g_pooled[i] = 0.f;
}

// ---------------- m = h @ W[layer] via bf16x3 tensor cores; zeroes agg ------
// 8 warps, warp w owns output dims [8w, 8w+8). 16-node M-tiles.
__global__ __launch_bounds__(256, 1)
void k_mgemm(const float* __restrict__ x, const float* __restrict__ W, int layer) {
    __shared__ __align__(16) __nv_bfloat16 s_hhi[16 * 72];
    __shared__ __align__(16) __nv_bfloat16 s_hlo[16 * 72];

    int tid = threadIdx.x;
    int wid = tid >> 5, lane = tid & 31;
    int tg = lane & 3, gid = lane >> 2;
    int dbase = wid * 8;
    int d0 = dbase + tg * 2;

    const float* Wl = W + layer * 64 * 64;
    // B[k][n] = Wl[k*64 + (dbase + gid)]
    unsigned Bhi[4][2], Blo[4][2];
#pragma unroll
    for (int kt = 0; kt < 4; kt++) {
        int k0 = kt * 16 + tg * 2;
        int nc = dbase + gid;
        split_pair(Wl[(k0)     * 64 + nc], Wl[(k0 + 1) * 64 + nc], Bhi[kt][0], Blo[kt][0]);
        split_pair(Wl[(k0 + 8) * 64 + nc], Wl[(k0 + 9) * 64 + nc], Bhi[kt][1], Blo[kt][1]);
    }

    const float* hin = layer ? g_h : x;

    // staging coords: one float4 per thread (16 rows x 64 cols = 256 float4)
    int srow = tid >> 4;
    int scol = (tid & 15) * 4;

    for (int chunk = blockIdx.x * 16; chunk < NN; chunk += gridDim.x * 16) {
        __syncthreads();
        {
            float4 v = *(const float4*)&hin[chunk * 64 + srow * 64 + scol];
            unsigned h01, l01, h23, l23;
            split2v(make_float2(v.x, v.y), h01, l01);
            split2v(make_float2(v.z, v.w), h23, l23);
            *(uint2*)&s_hhi[srow * 72 + scol] = make_uint2(h01, h23);
            *(uint2*)&s_hlo[srow * 72 + scol] = make_uint2(l01, l23);
        }
        __syncthreads();

        float C[4] = {0.f, 0.f, 0.f, 0.f};
#pragma unroll
        for (int kt = 0; kt < 4; kt++) {
            int k0 = kt * 16 + tg * 2;
            unsigned ahi[4], alo[4];
            ahi[0] = *(const unsigned*)&s_hhi[(gid)     * 72 + k0];
            ahi[1] = *(const unsigned*)&s_hhi[(gid + 8) * 72 + k0];
            ahi[2] = *(const unsigned*)&s_hhi[(gid)     * 72 + k0 + 8];
            ahi[3] = *(const unsigned*)&s_hhi[(gid + 8) * 72 + k0 + 8];
            alo[0] = *(const unsigned*)&s_hlo[(gid)     * 72 + k0];
            alo[1] = *(const unsigned*)&s_hlo[(gid + 8) * 72 + k0];
            alo[2] = *(const unsigned*)&s_hlo[(gid)     * 72 + k0 + 8];
            alo[3] = *(const unsigned*)&s_hlo[(gid + 8) * 72 + k0 + 8];
            mma16816(C, ahi, Bhi[kt]);
            mma16816(C, ahi, Blo[kt]);
            mma16816(C, alo, Bhi[kt]);
        }

#pragma unroll
        for (int p = 0; p < 2; p++) {
            int node = chunk + gid + p * 8;
            float2 mv = make_float2(C[p * 2], C[p * 2 + 1]);
            *(float2*)&g_m[node * 64 + d0] = mv;
            *(float2*)&g_agg[node * 64 + d0] = make_float2(0.f, 0.f);
        }
    }
}

// ---------------- edge scatter: agg[dst] += m[src] --------------------------
// 4 threads per edge, each owning 64B (4 x float4): 4 independent gathers +
// 4 independent RED.128 per thread for deep MLP.
__global__ void k_scatter(const int* __restrict__ ei) {
    int t = blockIdx.x * 256 + threadIdx.x;
    if (t >= NE * 4) return;
    int e = t >> 2;
    int sub = (t & 3) * 16;
    int src = ei[e];
    int dst = ei[NE + e];
    const float4* ps = (const float4*)&g_m[src * 64 + sub];
    float4* pd = (float4*)&g_agg[dst * 64 + sub];
    float4 a = ps[0], b = ps[1], c = ps[2], d = ps[3];
    atomicAdd(pd + 0, a);
    atomicAdd(pd + 1, b);
    atomicAdd(pd + 2, c);
    atomicAdd(pd + 3, d);
}

// ---------------- fused GRU gates via bf16x3 tensor cores -------------------
// Warp w owns d-slice [8w, 8w+8) of ALL six gate blocks -> full GRU
// elementwise epilogue stays in C-fragment registers.
__global__ __launch_bounds__(256, 1)
void k_gates(const float* __restrict__ x,
             const float* __restrict__ w_ih, const float* __restrict__ w_hh,
             const float* __restrict__ b_ih, const float* __restrict__ b_hh,
             const int* __restrict__ batch, int layer) {
    __shared__ __align__(16) __nv_bfloat16 s_ahi[16 * 72];
    __shared__ __align__(16) __nv_bfloat16 s_alo[16 * 72];
    __shared__ __align__(16) __nv_bfloat16 s_hhi[16 * 72];
    __shared__ __align__(16) __nv_bfloat16 s_hlo[16 * 72];
    __shared__ __align__(16) float s_hf[16 * 68];

    int tid = threadIdx.x;
    int wid = tid >> 5, lane = tid & 31;
    int tg = lane & 3, gid = lane >> 2;
    int dbase = wid * 8;
    int d0 = dbase + tg * 2;

    // B fragments: gates 0..2 = w_ih rows, 3..5 = w_hh rows.
    unsigned Bhi[6][4][2], Blo[6][4][2];
#pragma unroll
    for (int g = 0; g < 6; g++) {
        const float* wm = (g < 3) ? w_ih : w_hh;
        const float* wr = wm + ((g % 3) * 64 + dbase + gid) * 64;
#pragma unroll
        for (int kt = 0; kt < 4; kt++) {
            int k0 = kt * 16 + tg * 2;
            split_pair(wr[k0],     wr[k0 + 1], Bhi[g][kt][0], Blo[g][kt][0]);
            split_pair(wr[k0 + 8], wr[k0 + 9], Bhi[g][kt][1], Blo[g][kt][1]);
        }
    }
    float bi0[2], bi1[2], bi2[2], bh0[2], bh1[2], bh2[2];
#pragma unroll
    for (int j = 0; j < 2; j++) {
        bi0[j] = b_ih[d0 + j];       bh0[j] = b_hh[d0 + j];
        bi1[j] = b_ih[64 + d0 + j];  bh1[j] = b_hh[64 + d0 + j];
        bi2[j] = b_ih[128 + d0 + j]; bh2[j] = b_hh[128 + d0 + j];
    }

    const float* hin = layer ? g_h : x;

    // staging coords: one float4 per thread per array
    int srow = tid >> 4;
    int scol = (tid & 15) * 4;

    for (int chunk = blockIdx.x * 16; chunk < NN; chunk += gridDim.x * 16) {
        __syncthreads();
        {
            float4 va = *(const float4*)&g_agg[chunk * 64 + srow * 64 + scol];
            float4 vh = *(const float4*)&hin[chunk * 64 + srow * 64 + scol];
            unsigned h01, l01, h23, l23;
            split2v(make_float2(va.x, va.y), h01, l01);
            split2v(make_float2(va.z, va.w), h23, l23);
            *(uint2*)&s_ahi[srow * 72 + scol] = make_uint2(h01, h23);
            *(uint2*)&s_alo[srow * 72 + scol] = make_uint2(l01, l23);
            split2v(make_float2(vh.x, vh.y), h01, l01);
            split2v(make_float2(vh.z, vh.w), h23, l23);
            *(uint2*)&s_hhi[srow * 72 + scol] = make_uint2(h01, h23);
            *(uint2*)&s_hlo[srow * 72 + scol] = make_uint2(l01, l23);
            *(float4*)&s_hf[srow * 68 + scol] = vh;
        }
        __syncthreads();

        float C[6][4];
#pragma unroll
        for (int g = 0; g < 6; g++)
#pragma unroll
            for (int q = 0; q < 4; q++) C[g][q] = 0.f;

#pragma unroll
        for (int kt = 0; kt < 4; kt++) {
            int k0 = kt * 16 + tg * 2;
            unsigned ahi[4], alo[4];
            // agg tile -> gates 0..2 (i_r, i_z, i_n)
            ahi[0] = *(const unsigned*)&s_ahi[(gid)     * 72 + k0];
            ahi[1] = *(const unsigned*)&s_ahi[(gid + 8) * 72 + k0];
            ahi[2] = *(const unsigned*)&s_ahi[(gid)     * 72 + k0 + 8];
            ahi[3] = *(const unsigned*)&s_ahi[(gid + 8) * 72 + k0 + 8];
            alo[0] = *(const unsigned*)&s_alo[(gid)     * 72 + k0];
            alo[1] = *(const unsigned*)&s_alo[(gid + 8) * 72 + k0];
            alo[2] = *(const unsigned*)&s_alo[(gid)     * 72 + k0 + 8];
            alo[3] = *(const unsigned*)&s_alo[(gid + 8) * 72 + k0 + 8];
#pragma unroll
            for (int g = 0; g < 3; g++) {
                mma16816(C[g], ahi, Bhi[g][kt]);
                mma16816(C[g], ahi, Blo[g][kt]);
                mma16816(C[g], alo, Bhi[g][kt]);
            }
            // h tile -> gates 3..5 (h_r, h_z, h_n)
            ahi[0] = *(const unsigned*)&s_hhi[(gid)     * 72 + k0];
            ahi[1] = *(const unsigned*)&s_hhi[(gid + 8) * 72 + k0];
            ahi[2] = *(const unsigned*)&s_hhi[(gid)     * 72 + k0 + 8];
            ahi[3] = *(const unsigned*)&s_hhi[(gid + 8) * 72 + k0 + 8];
            alo[0] = *(const unsigned*)&s_hlo[(gid)     * 72 + k0];
            alo[1] = *(const unsigned*)&s_hlo[(gid + 8) * 72 + k0];
            alo[2] = *(const unsigned*)&s_hlo[(gid)     * 72 + k0 + 8];
            alo[3] = *(const unsigned*)&s_hlo[(gid + 8) * 72 + k0 + 8];
#pragma unroll
            for (int g = 3; g < 6; g++) {
                mma16816(C[g], ahi, Bhi[g][kt]);
                mma16816(C[g], ahi, Blo[g][kt]);
                mma16816(C[g], alo, Bhi[g][kt]);
            }
        }

        // GRU elementwise epilogue (per-thread: 2 rows x 2 dims)
#pragma unroll
        for (int p = 0; p < 2; p++) {
            int row = gid + p * 8;
            int node = chunk + row;
            float hv[2];
#pragma unroll
            for (int j = 0; j < 2; j++) {
                int q = p * 2 + j;
                float r  = sigf(C[0][q] + bi0[j] + C[3][q] + bh0[j]);
                float z  = sigf(C[1][q] + bi1[j] + C[4][q] + bh1[j]);
                float nn = tanhfast(C[2][q] + bi2[j] + r * (C[5][q] + bh2[j]));
                float ho = s_hf[row * 68 + d0 + j];
                hv[j] = (1.f - z) * nn + z * ho;
            }
            if (layer == 0) {
                *(float2*)&g_h[node * 64 + d0] = make_float2(hv[0], hv[1]);
            } else {
                float2 rv = make_float2(fmaxf(hv[0], 0.f), fmaxf(hv[1], 0.f));
                atomicAdd((float2*)&g_pooled[batch[node] * 64 + d0], rv);
            }
        }
    }
}

// ---------------- mean pool + fc1(relu) + fc2 + log_softmax -----------------
// batch_vector is sorted, so per-graph node counts come from binary search.
__device__ __forceinline__ int lbound(const int* __restrict__ b, int v) {
    int lo = 0, hi = NN;
    while (lo < hi) {
        int m = (lo + hi) >> 1;
        if (b[m] < v) lo = m + 1; else hi = m;
    }
    return lo;
}

__global__ void k_poolfc(const int* __restrict__ batch,
                         const float* __restrict__ fc1w, const float* __restrict__ fc1b,
                         const float* __restrict__ fc2w, const float* __restrict__ fc2b,
                         float* __restrict__ out) {
    int g = threadIdx.x;
    if (g >= NG) return;
    int cnt = lbound(batch, g + 1) - lbound(batch, g);
    float inv = 1.f / fmaxf((float)cnt, 1.f);
    float p[D];
#pragma unroll
    for (int k = 0; k < D; k++) p[k] = g_pooled[g * D + k] * inv;

    float y[DH];
#pragma unroll
    for (int j = 0; j < DH; j++) {
        float s = fc1b[j];
#pragma unroll
        for (int k = 0; k < D; k++) s += p[k] * fc1w[j * D + k];
        y[j] = fmaxf(s, 0.f);
    }

    float z[NC];
    float mx = -1e30f;
#pragma unroll
    for (int c = 0; c < NC; c++) {
        float s = fc2b[c];
#pragma unroll
        for (int j = 0; j < DH; j++) s += y[j] * fc2w[c * DH + j];
        z[c] = s;
        mx = fmaxf(mx, s);
    }
    float lse = 0.f;
#pragma unroll
    for (int c = 0; c < NC; c++) lse += expf(z[c] - mx);
    lse = logf(lse) + mx;
#pragma unroll
    for (int c = 0; c < NC; c++) out[g * NC + c] = z[c] - lse;
}

// ---------------- launch -----------------------------------------------------
extern "C" void kernel_launch(void* const* d_in, const int* in_sizes, int n_in,
                              void* d_out, int out_size) {
    const float* x     = (const float*)d_in[0];
    const int*   ei    = (const int*)d_in[1];
    const int*   batch = (const int*)d_in[2];
    const float* W     = (const float*)d_in[3];
    const float* w_ih  = (const float*)d_in[4];
    const float* w_hh  = (const float*)d_in[5];
    const float* b_ih  = (const float*)d_in[6];
    const float* b_hh  = (const float*)d_in[7];
    const float* fc1w  = (const float*)d_in[8];
    const float* fc1b  = (const float*)d_in[9];
    const float* fc2w  = (const float*)d_in[10];
    const float* fc2b  = (const float*)d_in[11];
    float* out = (float*)d_out;

    k_init<<<32, 256>>>();

    for (int l = 0; l < 2; l++) {
        k_mgemm<<<592, 256>>>(x, W, l);
        k_scatter<<<(NE * 4) / 256, 256>>>(ei);
        k_gates<<<296, 256>>>(x, w_ih, w_hh, b_ih, b_hh, batch, l);
    }
    k_poolfc<<<1, 128>>>(batch, fc1w, fc1b, fc2w, fc2b, out);
}

// round 10
// speedup vs baseline: 3.1076x; 1.2983x over previous
#include <cuda_runtime.h>
#include <cuda_bf16.h>
#include <math.h>

#define NN 50000
#define NE 800000
#define D  64
#define NG 128
#define DH 32
#define NC 6

// ---------------- scratch (device globals; no allocation allowed) ----------
__device__ float g_h[NN * D];       // hidden state
__device__ float g_m[NN * D];       // per-node messages m = h @ W[l]
__device__ float g_agg[NN * D];     // scatter-add destination
__device__ float g_pooled[NG * D];  // graph pooling sums

__device__ __forceinline__ float sigf(float x) {
    return __fdividef(1.f, 1.f + __expf(-x));
}
__device__ __forceinline__ float tanhfast(float x) {
    return __fdividef(2.f, 1.f + __expf(-2.f * x)) - 1.f;
}

// bf16 split helpers: v = hi + lo with |residual| ~ 2^-16 |v|
__device__ __forceinline__ void split1(float v, __nv_bfloat16& h, __nv_bfloat16& l) {
    h = __float2bfloat16(v);
    l = __float2bfloat16(v - __bfloat162float(h));
}
__device__ __forceinline__ void split_pair(float v0, float v1, unsigned& hi, unsigned& lo) {
    __nv_bfloat16 h0, l0, h1, l1;
    split1(v0, h0, l0);
    split1(v1, h1, l1);
    hi = (unsigned)__bfloat16_as_ushort(h0) | ((unsigned)__bfloat16_as_ushort(h1) << 16);
    lo = (unsigned)__bfloat16_as_ushort(l0) | ((unsigned)__bfloat16_as_ushort(l1) << 16);
}
// vector split: float2 -> (bf16x2 hi word, bf16x2 lo word)
__device__ __forceinline__ void split2v(float2 v, unsigned& hi, unsigned& lo) {
    __nv_bfloat162 h = __float22bfloat162_rn(v);
    float2 r = __bfloat1622float2(h);
    __nv_bfloat162 l = __float22bfloat162_rn(make_float2(v.x - r.x, v.y - r.y));
    hi = *(unsigned*)&h;
    lo = *(unsigned*)&l;
}

// mma.sync m16n8k16 bf16 -> f32 accumulate
__device__ __forceinline__ void mma16816(float* c, const unsigned* a, const unsigned* b) {
    asm volatile(
        "mma.sync.aligned.m16n8k16.row.col.f32.bf16.bf16.f32 "
        "{%0,%1,%2,%3}, {%4,%5,%6,%7}, {%8,%9}, {%0,%1,%2,%3};"
        : "+f"(c[0]), "+f"(c[1]), "+f"(c[2]), "+f"(c[3])
        : "r"(a[0]), "r"(a[1]), "r"(a[2]), "r"(a[3]), "r"(b[0]), "r"(b[1]));
}

// ---------------- init: zero pooled sums ------------------------------------
__global__ void k_init() {
    int i = blockIdx.x * 256 + threadIdx.x;
    if (i < NG * D) g_pooled[i] = 0.f;
}

// ---------------- m = h @ W[layer] via bf16x3 tensor cores; zeroes agg ------
// Double-buffered pipeline: prefetch next chunk's LDG before this chunk's MMAs.
__global__ __launch_bounds__(256, 1)
void k_mgemm(const float* __restrict__ x, const float* __restrict__ W, int layer) {
    __shared__ __align__(16) __nv_bfloat16 s_hhi[2][16 * 72];
    __shared__ __align__(16) __nv_bfloat16 s_hlo[2][16 * 72];

    int tid = threadIdx.x;
    int wid = tid >> 5, lane = tid & 31;
    int tg = lane & 3, gid = lane >> 2;
    int dbase = wid * 8;
    int d0 = dbase + tg * 2;

    const float* Wl = W + layer * 64 * 64;
    unsigned Bhi[4][2], Blo[4][2];
#pragma unroll
    for (int kt = 0; kt < 4; kt++) {
        int k0 = kt * 16 + tg * 2;
        int nc = dbase + gid;
        split_pair(Wl[(k0)     * 64 + nc], Wl[(k0 + 1) * 64 + nc], Bhi[kt][0], Blo[kt][0]);
        split_pair(Wl[(k0 + 8) * 64 + nc], Wl[(k0 + 9) * 64 + nc], Bhi[kt][1], Blo[kt][1]);
    }

    const float* hin = layer ? g_h : x;
    int srow = tid >> 4;
    int scol = (tid & 15) * 4;
    const int stride = gridDim.x * 16;

    int chunk = blockIdx.x * 16;
    float4 vh;
    if (chunk < NN) {
        vh = *(const float4*)&hin[chunk * 64 + srow * 64 + scol];
        unsigned h01, l01, h23, l23;
        split2v(make_float2(vh.x, vh.y), h01, l01);
        split2v(make_float2(vh.z, vh.w), h23, l23);
        *(uint2*)&s_hhi[0][srow * 72 + scol] = make_uint2(h01, h23);
        *(uint2*)&s_hlo[0][srow * 72 + scol] = make_uint2(l01, l23);
    }
    __syncthreads();

    for (int it = 0; chunk < NN; chunk += stride, it++) {
        int buf = it & 1;
        int next = chunk + stride;
        if (next < NN)
            vh = *(const float4*)&hin[next * 64 + srow * 64 + scol];

        float C[4] = {0.f, 0.f, 0.f, 0.f};
#pragma unroll
        for (int kt = 0; kt < 4; kt++) {
            int k0 = kt * 16 + tg * 2;
            unsigned ahi[4], alo[4];
            ahi[0] = *(const unsigned*)&s_hhi[buf][(gid)     * 72 + k0];
            ahi[1] = *(const unsigned*)&s_hhi[buf][(gid + 8) * 72 + k0];
            ahi[2] = *(const unsigned*)&s_hhi[buf][(gid)     * 72 + k0 + 8];
            ahi[3] = *(const unsigned*)&s_hhi[buf][(gid + 8) * 72 + k0 + 8];
            alo[0] = *(const unsigned*)&s_hlo[buf][(gid)     * 72 + k0];
            alo[1] = *(const unsigned*)&s_hlo[buf][(gid + 8) * 72 + k0];
            alo[2] = *(const unsigned*)&s_hlo[buf][(gid)     * 72 + k0 + 8];
            alo[3] = *(const unsigned*)&s_hlo[buf][(gid + 8) * 72 + k0 + 8];
            mma16816(C, ahi, Bhi[kt]);
            mma16816(C, ahi, Blo[kt]);
            mma16816(C, alo, Bhi[kt]);
        }

#pragma unroll
        for (int p = 0; p < 2; p++) {
            int node = chunk + gid + p * 8;
            *(float2*)&g_m[node * 64 + d0] = make_float2(C[p * 2], C[p * 2 + 1]);
            *(float2*)&g_agg[node * 64 + d0] = make_float2(0.f, 0.f);
        }

        if (next < NN) {
            unsigned h01, l01, h23, l23;
            split2v(make_float2(vh.x, vh.y), h01, l01);
            split2v(make_float2(vh.z, vh.w), h23, l23);
            *(uint2*)&s_hhi[buf ^ 1][srow * 72 + scol] = make_uint2(h01, h23);
            *(uint2*)&s_hlo[buf ^ 1][srow * 72 + scol] = make_uint2(l01, l23);
        }
        __syncthreads();
    }
}

// ---------------- edge scatter: agg[dst] += m[src] --------------------------
// (proven form: one thread per (edge, 16B quad), RED.128)
__global__ void k_scatter(const int* __restrict__ ei) {
    int t = blockIdx.x * 256 + threadIdx.x;
    if (t >= NE * 16) return;
    int e = t >> 4;
    int q = t & 15;
    int src = ei[e];
    int dst = ei[NE + e];
    float4 v = *reinterpret_cast<const float4*>(&g_m[src * 64 + q * 4]);
    atomicAdd(reinterpret_cast<float4*>(&g_agg[dst * 64 + q * 4]), v);
}

// ---------------- fused GRU gates via bf16x3 tensor cores -------------------
// Double-buffered pipeline; warp w owns d-slice [8w, 8w+8) of ALL six gates.
__global__ __launch_bounds__(256, 1)
void k_gates(const float* __restrict__ x,
             const float* __restrict__ w_ih, const float* __restrict__ w_hh,
             const float* __restrict__ b_ih, const float* __restrict__ b_hh,
             const int* __restrict__ batch, int layer) {
    __shared__ __align__(16) __nv_bfloat16 s_ahi[2][16 * 72];
    __shared__ __align__(16) __nv_bfloat16 s_alo[2][16 * 72];
    __shared__ __align__(16) __nv_bfloat16 s_hhi[2][16 * 72];
    __shared__ __align__(16) __nv_bfloat16 s_hlo[2][16 * 72];
    __shared__ __align__(16) float s_hf[2][16 * 68];

    int tid = threadIdx.x;
    int wid = tid >> 5, lane = tid & 31;
    int tg = lane & 3, gid = lane >> 2;
    int dbase = wid * 8;
    int d0 = dbase + tg * 2;

    unsigned Bhi[6][4][2], Blo[6][4][2];
#pragma unroll
    for (int g = 0; g < 6; g++) {
        const float* wm = (g < 3) ? w_ih : w_hh;
        const float* wr = wm + ((g % 3) * 64 + dbase + gid) * 64;
#pragma unroll
        for (int kt = 0; kt < 4; kt++) {
            int k0 = kt * 16 + tg * 2;
            split_pair(wr[k0],     wr[k0 + 1], Bhi[g][kt][0], Blo[g][kt][0]);
            split_pair(wr[k0 + 8], wr[k0 + 9], Bhi[g][kt][1], Blo[g][kt][1]);
        }
    }
    float bi0[2], bi1[2], bi2[2], bh0[2], bh1[2], bh2[2];
#pragma unroll
    for (int j = 0; j < 2; j++) {
        bi0[j] = b_ih[d0 + j];       bh0[j] = b_hh[d0 + j];
        bi1[j] = b_ih[64 + d0 + j];  bh1[j] = b_hh[64 + d0 + j];
        bi2[j] = b_ih[128 + d0 + j]; bh2[j] = b_hh[128 + d0 + j];
    }

    const float* hin = layer ? g_h : x;
    int srow = tid >> 4;
    int scol = (tid & 15) * 4;
    const int stride = gridDim.x * 16;

    int chunk = blockIdx.x * 16;
    float4 va, vh;
    if (chunk < NN) {
        va = *(const float4*)&g_agg[chunk * 64 + srow * 64 + scol];
        vh = *(const float4*)&hin[chunk * 64 + srow * 64 + scol];
        unsigned h01, l01, h23, l23;
        split2v(make_float2(va.x, va.y), h01, l01);
        split2v(make_float2(va.z, va.w), h23, l23);
        *(uint2*)&s_ahi[0][srow * 72 + scol] = make_uint2(h01, h23);
        *(uint2*)&s_alo[0][srow * 72 + scol] = make_uint2(l01, l23);
        split2v(make_float2(vh.x, vh.y), h01, l01);
        split2v(make_float2(vh.z, vh.w), h23, l23);
        *(uint2*)&s_hhi[0][srow * 72 + scol] = make_uint2(h01, h23);
        *(uint2*)&s_hlo[0][srow * 72 + scol] = make_uint2(l01, l23);
        *(float4*)&s_hf[0][srow * 68 + scol] = vh;
    }
    __syncthreads();

    for (int it = 0; chunk < NN; chunk += stride, it++) {
        int buf = it & 1;
        int next = chunk + stride;
        if (next < NN) {
            va = *(const float4*)&g_agg[next * 64 + srow * 64 + scol];
            vh = *(const float4*)&hin[next * 64 + srow * 64 + scol];
        }

        float C[6][4];
#pragma unroll
        for (int g = 0; g < 6; g++)
#pragma unroll
            for (int q = 0; q < 4; q++) C[g][q] = 0.f;

#pragma unroll
        for (int kt = 0; kt < 4; kt++) {
            int k0 = kt * 16 + tg * 2;
            unsigned ahi[4], alo[4];
            // agg tile -> gates 0..2 (i_r, i_z, i_n)
            ahi[0] = *(const unsigned*)&s_ahi[buf][(gid)     * 72 + k0];
            ahi[1] = *(const unsigned*)&s_ahi[buf][(gid + 8) * 72 + k0];
            ahi[2] = *(const unsigned*)&s_ahi[buf][(gid)     * 72 + k0 + 8];
            ahi[3] = *(const unsigned*)&s_ahi[buf][(gid + 8) * 72 + k0 + 8];
            alo[0] = *(const unsigned*)&s_alo[buf][(gid)     * 72 + k0];
            alo[1] = *(const unsigned*)&s_alo[buf][(gid + 8) * 72 + k0];
            alo[2] = *(const unsigned*)&s_alo[buf][(gid)     * 72 + k0 + 8];
            alo[3] = *(const unsigned*)&s_alo[buf][(gid + 8) * 72 + k0 + 8];
#pragma unroll
            for (int g = 0; g < 3; g++) {
                mma16816(C[g], ahi, Bhi[g][kt]);
                mma16816(C[g], ahi, Blo[g][kt]);
                mma16816(C[g], alo, Bhi[g][kt]);
            }
            // h tile -> gates 3..5 (h_r, h_z, h_n)
            ahi[0] = *(const unsigned*)&s_hhi[buf][(gid)     * 72 + k0];
            ahi[1] = *(const unsigned*)&s_hhi[buf][(gid + 8) * 72 + k0];
            ahi[2] = *(const unsigned*)&s_hhi[buf][(gid)     * 72 + k0 + 8];
            ahi[3] = *(const unsigned*)&s_hhi[buf][(gid + 8) * 72 + k0 + 8];
            alo[0] = *(const unsigned*)&s_hlo[buf][(gid)     * 72 + k0];
            alo[1] = *(const unsigned*)&s_hlo[buf][(gid + 8) * 72 + k0];
            alo[2] = *(const unsigned*)&s_hlo[buf][(gid)     * 72 + k0 + 8];
            alo[3] = *(const unsigned*)&s_hlo[buf][(gid + 8) * 72 + k0 + 8];
#pragma unroll
            for (int g = 3; g < 6; g++) {
                mma16816(C[g], ahi, Bhi[g][kt]);
                mma16816(C[g], ahi, Blo[g][kt]);
                mma16816(C[g], alo, Bhi[g][kt]);
            }
        }

        // GRU elementwise epilogue (per-thread: 2 rows x 2 dims)
#pragma unroll
        for (int p = 0; p < 2; p++) {
            int row = gid + p * 8;
            int node = chunk + row;
            float hv[2];
#pragma unroll
            for (int j = 0; j < 2; j++) {
                int q = p * 2 + j;
                float r  = sigf(C[0][q] + bi0[j] + C[3][q] + bh0[j]);
                float z  = sigf(C[1][q] + bi1[j] + C[4][q] + bh1[j]);
                float nn = tanhfast(C[2][q] + bi2[j] + r * (C[5][q] + bh2[j]));
                float ho = s_hf[buf][row * 68 + d0 + j];
                hv[j] = (1.f - z) * nn + z * ho;
            }
            if (layer == 0) {
                *(float2*)&g_h[node * 64 + d0] = make_float2(hv[0], hv[1]);
            } else {
                float2 rv = make_float2(fmaxf(hv[0], 0.f), fmaxf(hv[1], 0.f));
                atomicAdd((float2*)&g_pooled[batch[node] * 64 + d0], rv);
            }
        }

        if (next < NN) {
            unsigned h01, l01, h23, l23;
            split2v(make_float2(va.x, va.y), h01, l01);
            split2v(make_float2(va.z, va.w), h23, l23);
            *(uint2*)&s_ahi[buf ^ 1][srow * 72 + scol] = make_uint2(h01, h23);
            *(uint2*)&s_alo[buf ^ 1][srow * 72 + scol] = make_uint2(l01, l23);
            split2v(make_float2(vh.x, vh.y), h01, l01);
            split2v(make_float2(vh.z, vh.w), h23, l23);
            *(uint2*)&s_hhi[buf ^ 1][srow * 72 + scol] = make_uint2(h01, h23);
            *(uint2*)&s_hlo[buf ^ 1][srow * 72 + scol] = make_uint2(l01, l23);
            *(float4*)&s_hf[buf ^ 1][srow * 68 + scol] = vh;
        }
        __syncthreads();
    }
}

// ---------------- mean pool + fc1(relu) + fc2 + log_softmax -----------------
// batch_vector is sorted, so per-graph node counts come from binary search.
__device__ __forceinline__ int lbound(const int* __restrict__ b, int v) {
    int lo = 0, hi = NN;
    while (lo < hi) {
        int m = (lo + hi) >> 1;
        if (b[m] < v) lo = m + 1; else hi = m;
    }
    return lo;
}

__global__ void k_poolfc(const int* __restrict__ batch,
                         const float* __restrict__ fc1w, const float* __restrict__ fc1b,
                         const float* __restrict__ fc2w, const float* __restrict__ fc2b,
                         float* __restrict__ out) {
    int g = threadIdx.x;
    if (g >= NG) return;
    int cnt = lbound(batch, g + 1) - lbound(batch, g);
    float inv = 1.f / fmaxf((float)cnt, 1.f);
    float p[D];
#pragma unroll
    for (int k = 0; k < D; k++) p[k] = g_pooled[g * D + k] * inv;

    float y[DH];
#pragma unroll
    for (int j = 0; j < DH; j++) {
        float s = fc1b[j];
#pragma unroll
        for (int k = 0; k < D; k++) s += p[k] * fc1w[j * D + k];
        y[j] = fmaxf(s, 0.f);
    }

    float z[NC];
    float mx = -1e30f;
#pragma unroll
    for (int c = 0; c < NC; c++) {
        float s = fc2b[c];
#pragma unroll
        for (int j = 0; j < DH; j++) s += y[j] * fc2w[c * DH + j];
        z[c] = s;
        mx = fmaxf(mx, s);
    }
    float lse = 0.f;
#pragma unroll
    for (int c = 0; c < NC; c++) lse += expf(z[c] - mx);
    lse = logf(lse) + mx;
#pragma unroll
    for (int c = 0; c < NC; c++) out[g * NC + c] = z[c] - lse;
}

// ---------------- launch -----------------------------------------------------
extern "C" void kernel_launch(void* const* d_in, const int* in_sizes, int n_in,
                              void* d_out, int out_size) {
    const float* x     = (const float*)d_in[0];
    const int*   ei    = (const int*)d_in[1];
    const int*   batch = (const int*)d_in[2];
    const float* W     = (const float*)d_in[3];
    const float* w_ih  = (const float*)d_in[4];
    const float* w_hh  = (const float*)d_in[5];
    const float* b_ih  = (const float*)d_in[6];
    const float* b_hh  = (const float*)d_in[7];
    const float* fc1w  = (const float*)d_in[8];
    const float* fc1b  = (const float*)d_in[9];
    const float* fc2w  = (const float*)d_in[10];
    const float* fc2b  = (const float*)d_in[11];
    float* out = (float*)d_out;

    k_init<<<32, 256>>>();

    for (int l = 0; l < 2; l++) {
        k_mgemm<<<592, 256>>>(x, W, l);
        k_scatter<<<(NE * 16) / 256, 256>>>(ei);
        k_gates<<<148, 256>>>(x, w_ih, w_hh, b_ih, b_hh, batch, l);
    }
    k_poolfc<<<1, 128>>>(batch, fc1w, fc1b, fc2w, fc2b, out);
}

// round 11
// speedup vs baseline: 3.2482x; 1.0452x over previous
#include <cuda_runtime.h>
#include <cuda_bf16.h>
#include <math.h>

#define NN 50000
#define NE 800000
#define D  64
#define NG 128
#define DH 32
#define NC 6

// ---------------- scratch (device globals; no allocation allowed) ----------
__device__ float g_h[NN * D];       // hidden state
__device__ float g_m[NN * D];       // per-node messages m = h @ W[l]
__device__ float g_agg[NN * D];     // scatter-add destination
__device__ float g_pooled[NG * D];  // graph pooling sums

__device__ __forceinline__ float sigf(float x) {
    return __fdividef(1.f, 1.f + __expf(-x));
}
__device__ __forceinline__ float tanhfast(float x) {
    return __fdividef(2.f, 1.f + __expf(-2.f * x)) - 1.f;
}

// bf16 split helpers: v = hi + lo with |residual| ~ 2^-16 |v|
__device__ __forceinline__ void split1(float v, __nv_bfloat16& h, __nv_bfloat16& l) {
    h = __float2bfloat16(v);
    l = __float2bfloat16(v - __bfloat162float(h));
}
__device__ __forceinline__ void split_pair(float v0, float v1, unsigned& hi, unsigned& lo) {
    __nv_bfloat16 h0, l0, h1, l1;
    split1(v0, h0, l0);
    split1(v1, h1, l1);
    hi = (unsigned)__bfloat16_as_ushort(h0) | ((unsigned)__bfloat16_as_ushort(h1) << 16);
    lo = (unsigned)__bfloat16_as_ushort(l0) | ((unsigned)__bfloat16_as_ushort(l1) << 16);
}
// vector split: float2 -> (bf16x2 hi word, bf16x2 lo word)
__device__ __forceinline__ void split2v(float2 v, unsigned& hi, unsigned& lo) {
    __nv_bfloat162 h = __float22bfloat162_rn(v);
    float2 r = __bfloat1622float2(h);
    __nv_bfloat162 l = __float22bfloat162_rn(make_float2(v.x - r.x, v.y - r.y));
    hi = *(unsigned*)&h;
    lo = *(unsigned*)&l;
}

// mma.sync m16n8k16 bf16 -> f32 accumulate
__device__ __forceinline__ void mma16816(float* c, const unsigned* a, const unsigned* b) {
    asm volatile(
        "mma.sync.aligned.m16n8k16.row.col.f32.bf16.bf16.f32 "
        "{%0,%1,%2,%3}, {%4,%5,%6,%7}, {%8,%9}, {%0,%1,%2,%3};"
        : "+f"(c[0]), "+f"(c[1]), "+f"(c[2]), "+f"(c[3])
        : "r"(a[0]), "r"(a[1]), "r"(a[2]), "r"(a[3]), "r"(b[0]), "r"(b[1]));
}

// ---------------- init: zero pooled sums ------------------------------------
__global__ void k_init() {
    int i = blockIdx.x * 256 + threadIdx.x;
    if (i < NG * D) g_pooled[i] = 0.f;
}

// ---------------- m = h @ W[layer] via bf16x3 tensor cores; zeroes agg ------
// Double-buffered pipeline (unchanged from measured-good R10 version).
__global__ __launch_bounds__(256, 1)
void k_mgemm(const float* __restrict__ x, const float* __restrict__ W, int layer) {
    __shared__ __align__(16) __nv_bfloat16 s_hhi[2][16 * 72];
    __shared__ __align__(16) __nv_bfloat16 s_hlo[2][16 * 72];

    int tid = threadIdx.x;
    int wid = tid >> 5, lane = tid & 31;
    int tg = lane & 3, gid = lane >> 2;
    int dbase = wid * 8;
    int d0 = dbase + tg * 2;

    const float* Wl = W + layer * 64 * 64;
    unsigned Bhi[4][2], Blo[4][2];
#pragma unroll
    for (int kt = 0; kt < 4; kt++) {
        int k0 = kt * 16 + tg * 2;
        int nc = dbase + gid;
        split_pair(Wl[(k0)     * 64 + nc], Wl[(k0 + 1) * 64 + nc], Bhi[kt][0], Blo[kt][0]);
        split_pair(Wl[(k0 + 8) * 64 + nc], Wl[(k0 + 9) * 64 + nc], Bhi[kt][1], Blo[kt][1]);
    }

    const float* hin = layer ? g_h : x;
    int srow = tid >> 4;
    int scol = (tid & 15) * 4;
    const int stride = gridDim.x * 16;

    int chunk = blockIdx.x * 16;
    float4 vh;
    if (chunk < NN) {
        vh = *(const float4*)&hin[chunk * 64 + srow * 64 + scol];
        unsigned h01, l01, h23, l23;
        split2v(make_float2(vh.x, vh.y), h01, l01);
        split2v(make_float2(vh.z, vh.w), h23, l23);
        *(uint2*)&s_hhi[0][srow * 72 + scol] = make_uint2(h01, h23);
        *(uint2*)&s_hlo[0][srow * 72 + scol] = make_uint2(l01, l23);
    }
    __syncthreads();

    for (int it = 0; chunk < NN; chunk += stride, it++) {
        int buf = it & 1;
        int next = chunk + stride;
        if (next < NN)
            vh = *(const float4*)&hin[next * 64 + srow * 64 + scol];

        float C[4] = {0.f, 0.f, 0.f, 0.f};
#pragma unroll
        for (int kt = 0; kt < 4; kt++) {
            int k0 = kt * 16 + tg * 2;
            unsigned ahi[4], alo[4];
            ahi[0] = *(const unsigned*)&s_hhi[buf][(gid)     * 72 + k0];
            ahi[1] = *(const unsigned*)&s_hhi[buf][(gid + 8) * 72 + k0];
            ahi[2] = *(const unsigned*)&s_hhi[buf][(gid)     * 72 + k0 + 8];
            ahi[3] = *(const unsigned*)&s_hhi[buf][(gid + 8) * 72 + k0 + 8];
            alo[0] = *(const unsigned*)&s_hlo[buf][(gid)     * 72 + k0];
            alo[1] = *(const unsigned*)&s_hlo[buf][(gid + 8) * 72 + k0];
            alo[2] = *(const unsigned*)&s_hlo[buf][(gid)     * 72 + k0 + 8];
            alo[3] = *(const unsigned*)&s_hlo[buf][(gid + 8) * 72 + k0 + 8];
            mma16816(C, ahi, Bhi[kt]);
            mma16816(C, ahi, Blo[kt]);
            mma16816(C, alo, Bhi[kt]);
        }

#pragma unroll
        for (int p = 0; p < 2; p++) {
            int node = chunk + gid + p * 8;
            *(float2*)&g_m[node * 64 + d0] = make_float2(C[p * 2], C[p * 2 + 1]);
            *(float2*)&g_agg[node * 64 + d0] = make_float2(0.f, 0.f);
        }

        if (next < NN) {
            unsigned h01, l01, h23, l23;
            split2v(make_float2(vh.x, vh.y), h01, l01);
            split2v(make_float2(vh.z, vh.w), h23, l23);
            *(uint2*)&s_hhi[buf ^ 1][srow * 72 + scol] = make_uint2(h01, h23);
            *(uint2*)&s_hlo[buf ^ 1][srow * 72 + scol] = make_uint2(l01, l23);
        }
        __syncthreads();
    }
}

// ---------------- edge scatter: agg[dst] += m[src] --------------------------
// (proven form: one thread per (edge, 16B quad), RED.128)
__global__ void k_scatter(const int* __restrict__ ei) {
    int t = blockIdx.x * 256 + threadIdx.x;
    if (t >= NE * 16) return;
    int e = t >> 4;
    int q = t & 15;
    int src = ei[e];
    int dst = ei[NE + e];
    float4 v = *reinterpret_cast<const float4*>(&g_m[src * 64 + q * 4]);
    atomicAdd(reinterpret_cast<float4*>(&g_agg[dst * 64 + q * 4]), v);
}

// ---------------- fused GRU gates, 16-warp split ownership ------------------
// Warps 0-7: agg-side gates (i_r,i_z,i_n) with w_ih; warps 8-15: h-side gates
// (h_r,h_z,h_n) with w_hh. B-fragments halve to 48 regs/thread -> 512 threads
// fit the register file (4 warps/SMSP on the tensor pipe). C fragments are
// exchanged through smem sC[6][16][72]; epilogue reads coalesced float2s.
#define GATES_SMEM (4 * (2 * 1152) * 2 + 2 * 1088 * 4 + 6 * 16 * 72 * 4)

__global__ __launch_bounds__(512, 1)
void k_gates(const float* __restrict__ x,
             const float* __restrict__ w_ih, const float* __restrict__ w_hh,
             const float* __restrict__ b_ih, const float* __restrict__ b_hh,
             const int* __restrict__ batch, int layer) {
    extern __shared__ __align__(16) char smraw[];
    __nv_bfloat16* s_ahi = (__nv_bfloat16*)smraw;      // [2][16*72]
    __nv_bfloat16* s_alo = s_ahi + 2 * 1152;
    __nv_bfloat16* s_hhi = s_alo + 2 * 1152;
    __nv_bfloat16* s_hlo = s_hhi + 2 * 1152;
    float* s_hf = (float*)(s_hlo + 2 * 1152);          // [2][16*68]
    float* sC   = s_hf + 2 * 1088;                     // [6][16][72]

    int tid = threadIdx.x;
    int wid = tid >> 5, lane = tid & 31;
    int side = wid >> 3, w8 = wid & 7;
    int tg = lane & 3, gid = lane >> 2;
    int d0 = w8 * 8 + tg * 2;

    // B fragments: this warp's side only (3 gates) -> 48 regs.
    const float* wm = side ? w_hh : w_ih;
    unsigned Bhi[3][4][2], Blo[3][4][2];
#pragma unroll
    for (int g = 0; g < 3; g++) {
        const float* wr = wm + (g * 64 + w8 * 8 + gid) * 64;
#pragma unroll
        for (int kt = 0; kt < 4; kt++) {
            int k0 = kt * 16 + tg * 2;
            split_pair(wr[k0],     wr[k0 + 1], Bhi[g][kt][0], Blo[g][kt][0]);
            split_pair(wr[k0 + 8], wr[k0 + 9], Bhi[g][kt][1], Blo[g][kt][1]);
        }
    }

    // epilogue/staging coords: all 512 threads cover 16 rows x 32 col-pairs
    int srow = tid >> 5;          // 0..15
    int scol = lane * 2;          // 0..62
    float2 ebi0 = *(const float2*)&b_ih[scol];
    float2 ebi1 = *(const float2*)&b_ih[64 + scol];
    float2 ebi2 = *(const float2*)&b_ih[128 + scol];
    float2 ebh0 = *(const float2*)&b_hh[scol];
    float2 ebh1 = *(const float2*)&b_hh[64 + scol];
    float2 ebh2 = *(const float2*)&b_hh[128 + scol];

    const float* hin = layer ? g_h : x;
    const __nv_bfloat16* pAhi = side ? s_hhi : s_ahi;
    const __nv_bfloat16* pAlo = side ? s_hlo : s_alo;
    const int stride = gridDim.x * 16;

    int chunk = blockIdx.x * 16;
    float2 va, vh;
    if (chunk < NN) {
        va = *(const float2*)&g_agg[(chunk + srow) * 64 + scol];
        vh = *(const float2*)&hin[(chunk + srow) * 64 + scol];
        unsigned hi, lo;
        split2v(va, hi, lo);
        *(unsigned*)&s_ahi[srow * 72 + scol] = hi;
        *(unsigned*)&s_alo[srow * 72 + scol] = lo;
        split2v(vh, hi, lo);
        *(unsigned*)&s_hhi[srow * 72 + scol] = hi;
        *(unsigned*)&s_hlo[srow * 72 + scol] = lo;
        *(float2*)&s_hf[srow * 68 + scol] = vh;
    }
    __syncthreads();

    for (int it = 0; chunk < NN; chunk += stride, it++) {
        int buf = it & 1;
        int abase = buf * 1152;
        int next = chunk + stride;
        if (next < NN) {
            va = *(const float2*)&g_agg[(next + srow) * 64 + scol];
            vh = *(const float2*)&hin[(next + srow) * 64 + scol];
        }

        float C[3][4];
#pragma unroll
        for (int g = 0; g < 3; g++)
#pragma unroll
            for (int q = 0; q < 4; q++) C[g][q] = 0.f;

#pragma unroll
        for (int kt = 0; kt < 4; kt++) {
            int k0 = kt * 16 + tg * 2;
            unsigned ahi[4], alo[4];
            ahi[0] = *(const unsigned*)&pAhi[abase + (gid)     * 72 + k0];
            ahi[1] = *(const unsigned*)&pAhi[abase + (gid + 8) * 72 + k0];
            ahi[2] = *(const unsigned*)&pAhi[abase + (gid)     * 72 + k0 + 8];
            ahi[3] = *(const unsigned*)&pAhi[abase + (gid + 8) * 72 + k0 + 8];
            alo[0] = *(const unsigned*)&pAlo[abase + (gid)     * 72 + k0];
            alo[1] = *(const unsigned*)&pAlo[abase + (gid + 8) * 72 + k0];
            alo[2] = *(const unsigned*)&pAlo[abase + (gid)     * 72 + k0 + 8];
            alo[3] = *(const unsigned*)&pAlo[abase + (gid + 8) * 72 + k0 + 8];
#pragma unroll
            for (int g = 0; g < 3; g++) {
                mma16816(C[g], ahi, Bhi[g][kt]);
                mma16816(C[g], ahi, Blo[g][kt]);
                mma16816(C[g], alo, Bhi[g][kt]);
            }
        }

        // publish C fragments to smem
#pragma unroll
        for (int g = 0; g < 3; g++)
#pragma unroll
            for (int p = 0; p < 2; p++)
                *(float2*)&sC[((side * 3 + g) * 16 + gid + p * 8) * 72 + d0] =
                    make_float2(C[g][2 * p], C[g][2 * p + 1]);
        __syncthreads();

        // epilogue: each thread owns (row srow, cols scol..scol+1)
        {
            int node = chunk + srow;
            float2 ir = *(float2*)&sC[(0 * 16 + srow) * 72 + scol];
            float2 iz = *(float2*)&sC[(1 * 16 + srow) * 72 + scol];
            float2 ix = *(float2*)&sC[(2 * 16 + srow) * 72 + scol];
            float2 hr = *(float2*)&sC[(3 * 16 + srow) * 72 + scol];
            float2 hz = *(float2*)&sC[(4 * 16 + srow) * 72 + scol];
            float2 hn = *(float2*)&sC[(5 * 16 + srow) * 72 + scol];
            float2 ho = *(float2*)&s_hf[buf * 1088 + srow * 68 + scol];

            float r0 = sigf(ir.x + ebi0.x + hr.x + ebh0.x);
            float z0 = sigf(iz.x + ebi1.x + hz.x + ebh1.x);
            float n0 = tanhfast(ix.x + ebi2.x + r0 * (hn.x + ebh2.x));
            float h0 = (1.f - z0) * n0 + z0 * ho.x;
            float r1 = sigf(ir.y + ebi0.y + hr.y + ebh0.y);
            float z1 = sigf(iz.y + ebi1.y + hz.y + ebh1.y);
            float n1 = tanhfast(ix.y + ebi2.y + r1 * (hn.y + ebh2.y));
            float h1 = (1.f - z1) * n1 + z1 * ho.y;

            if (layer == 0) {
                *(float2*)&g_h[node * 64 + scol] = make_float2(h0, h1);
            } else {
                float2 rv = make_float2(fmaxf(h0, 0.f), fmaxf(h1, 0.f));
                atomicAdd((float2*)&g_pooled[batch[node] * 64 + scol], rv);
            }
        }

        // stage next chunk into the other buffer
        if (next < NN) {
            unsigned hi, lo;
            split2v(va, hi, lo);
            *(unsigned*)&s_ahi[(buf ^ 1) * 1152 + srow * 72 + scol] = hi;
            *(unsigned*)&s_alo[(buf ^ 1) * 1152 + srow * 72 + scol] = lo;
            split2v(vh, hi, lo);
            *(unsigned*)&s_hhi[(buf ^ 1) * 1152 + srow * 72 + scol] = hi;
            *(unsigned*)&s_hlo[(buf ^ 1) * 1152 + srow * 72 + scol] = lo;
            *(float2*)&s_hf[(buf ^ 1) * 1088 + srow * 68 + scol] = vh;
        }
        __syncthreads();
    }
}

// ---------------- mean pool + fc1(relu) + fc2 + log_softmax -----------------
__device__ __forceinline__ int lbound(const int* __restrict__ b, int v) {
    int lo = 0, hi = NN;
    while (lo < hi) {
        int m = (lo + hi) >> 1;
        if (b[m] < v) lo = m + 1; else hi = m;
    }
    return lo;
}

__global__ void k_poolfc(const int* __restrict__ batch,
                         const float* __restrict__ fc1w, const float* __restrict__ fc1b,
                         const float* __restrict__ fc2w, const float* __restrict__ fc2b,
                         float* __restrict__ out) {
    int g = threadIdx.x;
    if (g >= NG) return;
    int cnt = lbound(batch, g + 1) - lbound(batch, g);
    float inv = 1.f / fmaxf((float)cnt, 1.f);
    float p[D];
#pragma unroll
    for (int k = 0; k < D; k++) p[k] = g_pooled[g * D + k] * inv;

    float y[DH];
#pragma unroll
    for (int j = 0; j < DH; j++) {
        float s = fc1b[j];
#pragma unroll
        for (int k = 0; k < D; k++) s += p[k] * fc1w[j * D + k];
        y[j] = fmaxf(s, 0.f);
    }

    float z[NC];
    float mx = -1e30f;
#pragma unroll
    for (int c = 0; c < NC; c++) {
        float s = fc2b[c];
#pragma unroll
        for (int j = 0; j < DH; j++) s += y[j] * fc2w[c * DH + j];
        z[c] = s;
        mx = fmaxf(mx, s);
    }
    float lse = 0.f;
#pragma unroll
    for (int c = 0; c < NC; c++) lse += expf(z[c] - mx);
    lse = logf(lse) + mx;
#pragma unroll
    for (int c = 0; c < NC; c++) out[g * NC + c] = z[c] - lse;
}

// ---------------- launch -----------------------------------------------------
extern "C" void kernel_launch(void* const* d_in, const int* in_sizes, int n_in,
                              void* d_out, int out_size) {
    const float* x     = (const float*)d_in[0];
    const int*   ei    = (const int*)d_in[1];
    const int*   batch = (const int*)d_in[2];
    const float* W     = (const float*)d_in[3];
    const float* w_ih  = (const float*)d_in[4];
    const float* w_hh  = (const float*)d_in[5];
    const float* b_ih  = (const float*)d_in[6];
    const float* b_hh  = (const float*)d_in[7];
    const float* fc1w  = (const float*)d_in[8];
    const float* fc1b  = (const float*)d_in[9];
    const float* fc2w  = (const float*)d_in[10];
    const float* fc2b  = (const float*)d_in[11];
    float* out = (float*)d_out;

    cudaFuncSetAttribute(k_gates, cudaFuncAttributeMaxDynamicSharedMemorySize,
                         GATES_SMEM);

    k_init<<<32, 256>>>();

    for (int l = 0; l < 2; l++) {
        k_mgemm<<<592, 256>>>(x, W, l);
        k_scatter<<<(NE * 16) / 256, 256>>>(ei);
        k_gates<<<148, 512, GATES_SMEM>>>(x, w_ih, w_hh, b_ih, b_hh, batch, l);
    }
    k_poolfc<<<1, 128>>>(batch, fc1w, fc1b, fc2w, fc2b, out);
}